// round 4
// baseline (speedup 1.0000x reference)
#include <cuda_runtime.h>
#include <cuda_fp16.h>
#include <cstdint>

#define DD  1024
#define NB  64
#define NKK 512
#define MROWS (NB * NKK)          // 32768 flattened z-rows

// ---------------- device scratch (no allocs allowed) ----------------
__device__ __half g_wzT[DD * DD];            // w_z transposed fp16: [e][d]
__device__ __half g_xh[(size_t)MROWS * DD];  // z in fp16, batch-flattened
__device__ float  g_c[NB * DD];              // c[b,e] = u[b] . w_u[:,e] (fp32 exact)
__device__ float  g_qp[4 * MROWS];           // partial q per n-tile

// ---------------- helpers ----------------
static __device__ __forceinline__ uint32_t smem_u32(const void* p) {
    uint32_t a;
    asm("{ .reg .u64 t; cvta.to.shared.u64 t, %1; cvt.u32.u64 %0, t; }" : "=r"(a) : "l"(p));
    return a;
}
#define CP16(dst, src) \
    asm volatile("cp.async.cg.shared.global [%0], [%1], 16;" :: "r"(dst), "l"(src))
#define CP_COMMIT() asm volatile("cp.async.commit_group;" ::: "memory")
#define CP_WAIT(n)  asm volatile("cp.async.wait_group %0;" :: "n"(n) : "memory")

#define LDSM_X4(r0, r1, r2, r3, addr) \
    asm volatile("ldmatrix.sync.aligned.m8n8.x4.shared.b16 {%0,%1,%2,%3}, [%4];" \
        : "=r"(r0), "=r"(r1), "=r"(r2), "=r"(r3) : "r"(addr))

#define MMA16816(d, a, b) \
    asm volatile("mma.sync.aligned.m16n8k16.row.col.f32.f16.f16.f32 " \
        "{%0,%1,%2,%3}, {%4,%5,%6,%7}, {%8,%9}, {%0,%1,%2,%3};" \
        : "+f"((d)[0]), "+f"((d)[1]), "+f"((d)[2]), "+f"((d)[3]) \
        : "r"((a)[0]), "r"((a)[1]), "r"((a)[2]), "r"((a)[3]), "r"((b)[0]), "r"((b)[1]))

// exact identity tanh(x) = 1 - 2/(e^{2x}+1), via ex2.approx + rcp.approx (~1e-6)
static __device__ __forceinline__ float fast_tanh(float x) {
    float e;
    asm("ex2.approx.f32 %0, %1;" : "=f"(e) : "f"(x * 2.885390081777927f)); // 2*log2(e)
    float r;
    asm("rcp.approx.f32 %0, %1;" : "=f"(r) : "f"(e + 1.0f));
    return fmaf(-2.0f, r, 1.0f);
}

// ---------------- SMEM layout of the main kernel (XOR-swizzled 128B rows) --------
static constexpr int SA_ST   = 128 * 128;              // 16 KB per stage
static constexpr int SB_ST   = 256 * 128;              // 32 KB per stage
static constexpr int OFF_SA  = 0;
static constexpr int OFF_SB  = 3 * SA_ST;              // 49152
static constexpr int OFF_C   = OFF_SB + 3 * SB_ST;     // 147456
static constexpr int OFF_BI  = OFF_C + 1024;
static constexpr int OFF_QB  = OFF_BI + 1024;
static constexpr int SMEM_MAIN = OFF_QB + 2048;        // 151552

// ---------------- fused prep kernel: xhalf | transpose | cvec ----------------
// blocks [0,8192): z->fp16 ; [8192,9216): w_z transpose+fp16 ; [9216,9280): c vec
__global__ void __launch_bounds__(256) prep_kernel(const float* __restrict__ x,
                                                   const float* __restrict__ W) {
    __shared__ float psm[4 * DD];    // 16 KB, unioned across roles
    const int bid = blockIdx.x, t = threadIdx.x;

    if (bid < 8192) {                 // ---- xhalf ----
        size_t g = (size_t)bid * 256 + t;   // float4 index
#pragma unroll
        for (int j = 0; j < 4; j++, g += 2097152) {
            size_t m  = g >> 8;
            int    c4 = (int)(g & 255);
            size_t b  = m >> 9, k = m & 511;
            float4 v = __ldg(reinterpret_cast<const float4*>(x + ((b * 513 + 1 + k) << 10)) + c4);
            __half2 h0 = __floats2half2_rn(v.x, v.y);
            __half2 h1 = __floats2half2_rn(v.z, v.w);
            uint32_t* dst = reinterpret_cast<uint32_t*>(g_xh + (m << 10)) + c4 * 2;
            dst[0] = *reinterpret_cast<uint32_t*>(&h0);
            dst[1] = *reinterpret_cast<uint32_t*>(&h1);
        }
    } else if (bid < 9216) {          // ---- transpose w_z -> g_wzT fp16 ----
        float (*tile)[33] = reinterpret_cast<float (*)[33]>(psm);
        const int idx = bid - 8192;
        const int d0 = (idx & 31) * 32, e0 = (idx >> 5) * 32;
        const int tx = t & 31, ty = t >> 5;          // (32, 8)
#pragma unroll
        for (int i = 0; i < 32; i += 8)
            tile[ty + i][tx] = W[(size_t)(d0 + ty + i) * DD + e0 + tx];
        __syncthreads();
#pragma unroll
        for (int i = 0; i < 32; i += 8)
            g_wzT[(size_t)(e0 + ty + i) * DD + d0 + tx] = __float2half(tile[tx][ty + i]);
    } else {                          // ---- cvec: c[b,e] = u[b] . w_u[:,e] ----
        const int idx = bid - 9216;                  // grid (4, 16)
        const int e  = (idx & 3) * 256 + t;
        const int b0 = (idx >> 2) * 4;
        float (*us)[DD] = reinterpret_cast<float (*)[DD]>(psm);
        for (int i = t; i < 4 * DD; i += 256) {
            int j = i >> 10, d = i & (DD - 1);
            us[j][d] = x[(size_t)(b0 + j) * 513 * DD + d];
        }
        __syncthreads();
        const float* wu = W + (size_t)DD * DD;
        float a0 = 0, a1 = 0, a2 = 0, a3 = 0;
#pragma unroll 4
        for (int d = 0; d < DD; d++) {
            float w = __ldg(wu + (size_t)d * DD + e);
            a0 = fmaf(us[0][d], w, a0);
            a1 = fmaf(us[1][d], w, a1);
            a2 = fmaf(us[2][d], w, a2);
            a3 = fmaf(us[3][d], w, a3);
        }
        g_c[(b0 + 0) * DD + e] = a0;
        g_c[(b0 + 1) * DD + e] = a1;
        g_c[(b0 + 2) * DD + e] = a2;
        g_c[(b0 + 3) * DD + e] = a3;
    }
}

// ---------------- kernel 1: fused GEMM(mma.16816) + tanh + bias-dot ----------------
// grid = 1024: mtile(256) x ntile(4). CTA 512 thr: tile M=128 x N=256, K=1024.
// 3-stage cp.async pipeline, ONE __syncthreads per K-chunk.
__global__ void __launch_bounds__(512, 1) main_kernel(const float* __restrict__ bias) {
    extern __shared__ char smem[];
    const uint32_t sb = smem_u32(smem);
    const int tid  = threadIdx.x;
    const int w    = tid >> 5, lane = tid & 31;
    const int wm   = w >> 2,  wn   = w & 3;
    const int nt    = blockIdx.x & 3;
    const int m0    = (blockIdx.x >> 2) * 128;
    const int b     = m0 >> 9;

    float* c_sm  = reinterpret_cast<float*>(smem + OFF_C);
    float* bi_sm = reinterpret_cast<float*>(smem + OFF_BI);
    if (tid < 256) {
        c_sm[tid]  = g_c[b * DD + nt * 256 + tid];
        bi_sm[tid] = bias[nt * 256 + tid];
    }

    const __half* Ab = g_xh  + (size_t)m0 * DD;
    const __half* Bb = g_wzT + (size_t)nt * 256 * DD;

    // swizzled store: phys 16B-chunk = v ^ (row & 7)
    auto issue = [&](int kc, int s) {
#pragma unroll
        for (int j = 0; j < 2; j++) {   // A: 128 rows x 8 segs
            int i = tid + j * 512;
            int row = i >> 3, v = i & 7;
            uint32_t dst = sb + OFF_SA + s * SA_ST + row * 128 + ((v ^ (row & 7)) << 4);
            CP16(dst, Ab + (size_t)row * DD + kc * 64 + v * 8);
        }
#pragma unroll
        for (int j = 0; j < 4; j++) {   // B: 256 rows x 8 segs
            int i = tid + j * 512;
            int row = i >> 3, v = i & 7;
            uint32_t dst = sb + OFF_SB + s * SB_ST + row * 128 + ((v ^ (row & 7)) << 4);
            CP16(dst, Bb + (size_t)row * DD + kc * 64 + v * 8);
        }
        CP_COMMIT();
    };

    float acc[2][8][4];
#pragma unroll
    for (int mi = 0; mi < 2; mi++)
#pragma unroll
        for (int nj = 0; nj < 8; nj++)
#pragma unroll
            for (int r = 0; r < 4; r++) acc[mi][nj][r] = 0.0f;

    // per-lane ldmatrix geometry (local rows within warp tiles)
    const int aRow  = wm * 32 + (lane & 15);            // + mi*16
    const int aBit  = lane >> 4;                        // k 16B-subchunk select
    const int aSw   = aRow & 7;
    const int bRowL = (lane & 7) + ((lane >> 4) << 3);  // + wn*64 + g*16
    const int bBit  = (lane >> 3) & 1;

    issue(0, 0);
    issue(1, 1);

    for (int kc = 0; kc < 16; kc++) {
        if (kc == 15) { CP_WAIT(0); } else { CP_WAIT(1); }
        __syncthreads();
        if (kc < 14) issue(kc + 2, (kc + 2) % 3);

        const int s = kc % 3;
        const uint32_t aBase = sb + OFF_SA + s * SA_ST + aRow * 128;
        const uint32_t bBase = sb + OFF_SB + s * SB_ST;
#pragma unroll
        for (int ks = 0; ks < 4; ks++) {
            uint32_t a[2][4];
#pragma unroll
            for (int mi = 0; mi < 2; mi++) {
                uint32_t addr = aBase + mi * (16 * 128) + ((((ks * 2) + aBit) ^ aSw) << 4);
                LDSM_X4(a[mi][0], a[mi][1], a[mi][2], a[mi][3], addr);
            }
            uint32_t bf[8][2];
#pragma unroll
            for (int g = 0; g < 4; g++) {
                const int nrow = wn * 64 + g * 16 + bRowL;
                uint32_t addr = bBase + nrow * 128 + ((((ks * 2) + bBit) ^ (nrow & 7)) << 4);
                uint32_t r0, r1, r2, r3;
                LDSM_X4(r0, r1, r2, r3, addr);
                bf[2 * g][0] = r0; bf[2 * g][1] = r1;
                bf[2 * g + 1][0] = r2; bf[2 * g + 1][1] = r3;
            }
#pragma unroll
            for (int mi = 0; mi < 2; mi++)
#pragma unroll
                for (int nj = 0; nj < 8; nj++)
                    MMA16816(acc[mi][nj], a[mi], bf[nj]);
        }
    }

    // ---- epilogue (all in registers): +c -> tanh -> *bias -> row partials ----
    const int colb = wn * 64 + 2 * (lane & 3);
    float p[4] = {0.f, 0.f, 0.f, 0.f};
#pragma unroll
    for (int mi = 0; mi < 2; mi++)
#pragma unroll
        for (int nj = 0; nj < 8; nj++) {
            const int c0 = colb + nj * 8;
            p[2 * mi + 0] = fmaf(fast_tanh(acc[mi][nj][0] + c_sm[c0]),     bi_sm[c0],     p[2 * mi + 0]);
            p[2 * mi + 0] = fmaf(fast_tanh(acc[mi][nj][1] + c_sm[c0 + 1]), bi_sm[c0 + 1], p[2 * mi + 0]);
            p[2 * mi + 1] = fmaf(fast_tanh(acc[mi][nj][2] + c_sm[c0]),     bi_sm[c0],     p[2 * mi + 1]);
            p[2 * mi + 1] = fmaf(fast_tanh(acc[mi][nj][3] + c_sm[c0 + 1]), bi_sm[c0 + 1], p[2 * mi + 1]);
        }
#pragma unroll
    for (int i = 0; i < 4; i++) {
        p[i] += __shfl_xor_sync(0xffffffffu, p[i], 1);
        p[i] += __shfl_xor_sync(0xffffffffu, p[i], 2);
    }
    float* qb = reinterpret_cast<float*>(smem + OFF_QB);
    if ((lane & 3) == 0) {
        const int r = wm * 32 + (lane >> 2);
        qb[wn * 128 + r +  0] = p[0];   // rows r, r+8 from A-frag 0
        qb[wn * 128 + r +  8] = p[1];
        qb[wn * 128 + r + 16] = p[2];   // rows r+16, r+24 from A-frag 1
        qb[wn * 128 + r + 24] = p[3];
    }
    __syncthreads();
    if (tid < 128) {
        float s = qb[tid] + qb[128 + tid] + qb[256 + tid] + qb[384 + tid];
        g_qp[(size_t)nt * MROWS + m0 + tid] = s;
    }
}

// ---------------- kernel 2: softmax over k=512 per batch ----------------
__global__ void __launch_bounds__(512) softmax_kernel(float* __restrict__ out) {
    __shared__ float sred[16];
    __shared__ float sbc;
    const int b = blockIdx.x, t = threadIdx.x;
    const int wid = t >> 5, lid = t & 31;
    const int idx = b * NKK + t;
    float v = g_qp[idx] + g_qp[MROWS + idx] + g_qp[2 * MROWS + idx] + g_qp[3 * MROWS + idx];

    float m = v;
#pragma unroll
    for (int o = 16; o; o >>= 1) m = fmaxf(m, __shfl_xor_sync(0xffffffffu, m, o));
    if (lid == 0) sred[wid] = m;
    __syncthreads();
    if (wid == 0) {
        float mm = (lid < 16) ? sred[lid] : -1e30f;
#pragma unroll
        for (int o = 16; o; o >>= 1) mm = fmaxf(mm, __shfl_xor_sync(0xffffffffu, mm, o));
        if (lid == 0) sbc = mm;
    }
    __syncthreads();
    const float M = sbc;
    float e;
    asm("ex2.approx.f32 %0, %1;" : "=f"(e) : "f"((v - M) * 1.4426950408889634f));
    float s = e;
#pragma unroll
    for (int o = 16; o; o >>= 1) s += __shfl_xor_sync(0xffffffffu, s, o);
    __syncthreads();
    if (lid == 0) sred[wid] = s;
    __syncthreads();
    if (wid == 0) {
        float ss = (lid < 16) ? sred[lid] : 0.f;
#pragma unroll
        for (int o = 16; o; o >>= 1) ss += __shfl_xor_sync(0xffffffffu, ss, o);
        if (lid == 0) sbc = ss;
    }
    __syncthreads();
    out[idx] = e / sbc;
}

// ---------------- launch ----------------
extern "C" void kernel_launch(void* const* d_in, const int* in_sizes, int n_in,
                              void* d_out, int out_size) {
    const float* x    = (const float*)d_in[0];
    const float* W    = (const float*)d_in[1];
    const float* bias = (const float*)d_in[2];
    float* out = (float*)d_out;

    cudaFuncSetAttribute(main_kernel, cudaFuncAttributeMaxDynamicSharedMemorySize, SMEM_MAIN);

    prep_kernel<<<9280, 256>>>(x, W);
    main_kernel<<<1024, 512, SMEM_MAIN>>>(bias);
    softmax_kernel<<<64, 512>>>(out);
}

// round 5
// speedup vs baseline: 1.5635x; 1.5635x over previous
#include <cuda_runtime.h>
#include <cuda_fp16.h>
#include <cstdint>

#define DD  1024
#define NB  64
#define NKK 512
#define MROWS (NB * NKK)          // 32768 flattened z-rows

// ---------------- device scratch (no allocs allowed) ----------------
__device__ __half g_wzT[DD * DD];            // w_z transposed fp16: [e][d]
__device__ float  g_c[4][NB * DD];           // split-K partials of c[b,e]
__device__ float  g_qp[4 * MROWS];           // partial q per n-tile

// ---------------- helpers ----------------
static __device__ __forceinline__ uint32_t smem_u32(const void* p) {
    uint32_t a;
    asm("{ .reg .u64 t; cvta.to.shared.u64 t, %1; cvt.u32.u64 %0, t; }" : "=r"(a) : "l"(p));
    return a;
}
#define CP16(dst, src) \
    asm volatile("cp.async.cg.shared.global [%0], [%1], 16;" :: "r"(dst), "l"(src))
#define CP_COMMIT() asm volatile("cp.async.commit_group;" ::: "memory")
#define CP_WAIT(n)  asm volatile("cp.async.wait_group %0;" :: "n"(n) : "memory")

#define LDSM_X4(r0, r1, r2, r3, addr) \
    asm volatile("ldmatrix.sync.aligned.m8n8.x4.shared.b16 {%0,%1,%2,%3}, [%4];" \
        : "=r"(r0), "=r"(r1), "=r"(r2), "=r"(r3) : "r"(addr))

#define MMA16816(d, a, b0, b1) \
    asm volatile("mma.sync.aligned.m16n8k16.row.col.f32.f16.f16.f32 " \
        "{%0,%1,%2,%3}, {%4,%5,%6,%7}, {%8,%9}, {%0,%1,%2,%3};" \
        : "+f"((d)[0]), "+f"((d)[1]), "+f"((d)[2]), "+f"((d)[3]) \
        : "r"((a)[0]), "r"((a)[1]), "r"((a)[2]), "r"((a)[3]), "r"(b0), "r"(b1))

// exact identity tanh(x) = 1 - 2/(e^{2x}+1), via ex2.approx + rcp.approx (~1e-6)
static __device__ __forceinline__ float fast_tanh(float x) {
    float e;
    asm("ex2.approx.f32 %0, %1;" : "=f"(e) : "f"(x * 2.885390081777927f)); // 2*log2(e)
    float r;
    asm("rcp.approx.f32 %0, %1;" : "=f"(r) : "f"(e + 1.0f));
    return fmaf(-2.0f, r, 1.0f);
}

// ---------------- SMEM layout of the main kernel (XOR-swizzled 128B rows) --------
static constexpr int SA_ST   = 128 * 128;              // 16 KB per stage (fp16)
static constexpr int SB_ST   = 256 * 128;              // 32 KB per stage
static constexpr int OFF_SA  = 0;
static constexpr int OFF_SB  = 3 * SA_ST;              // 49152
static constexpr int OFF_C   = OFF_SB + 3 * SB_ST;     // 147456
static constexpr int OFF_BI  = OFF_C + 1024;
static constexpr int OFF_QB  = OFF_BI + 1024;
static constexpr int SMEM_MAIN = OFF_QB + 2048;        // 151552

// ---------------- prep kernel: w_z transpose->fp16 | split-K cvec ----------------
// blocks [0,1024): transpose ; [1024,1280): cvec partials (k-split by 4)
__global__ void __launch_bounds__(256) prep_kernel(const float* __restrict__ x,
                                                   const float* __restrict__ W) {
    __shared__ float psm[4 * 1056];    // union: 32x33 f32 tile | 4 x 1056 floats
    const int bid = blockIdx.x, t = threadIdx.x;

    if (bid < 1024) {                 // ---- transpose w_z -> g_wzT fp16 ----
        float (*tile)[33] = reinterpret_cast<float (*)[33]>(psm);
        const int d0 = (bid & 31) * 32, e0 = (bid >> 5) * 32;
        const int tx = t & 31, ty = t >> 5;          // (32, 8)
#pragma unroll
        for (int i = 0; i < 32; i += 8)
            tile[ty + i][tx] = W[(size_t)(d0 + ty + i) * DD + e0 + tx];
        __syncthreads();
#pragma unroll
        for (int i = 0; i < 32; i += 8)
            g_wzT[(size_t)(e0 + ty + i) * DD + d0 + tx] = __float2half(tile[tx][ty + i]);
    } else {                          // ---- cvec partial: sum over 256 d's ----
        const int idx = bid - 1024;                  // 256 blocks
        const int e  = (idx & 3) * 256 + t;          // e-chunk
        const int b0 = ((idx >> 2) & 15) * 4;        // 4 batches
        const int kq = idx >> 6;                     // d-quarter
        float (*us)[256] = reinterpret_cast<float (*)[256]>(psm);
        for (int i = t; i < 4 * 256; i += 256) {
            int j = i >> 8, d = i & 255;
            us[j][d] = x[(size_t)(b0 + j) * 513 * DD + kq * 256 + d];
        }
        __syncthreads();
        const float* wu = W + (size_t)DD * DD + (size_t)kq * 256 * DD;
        float a0 = 0, a1 = 0, a2 = 0, a3 = 0;
#pragma unroll 4
        for (int d = 0; d < 256; d++) {
            float w = __ldg(wu + (size_t)d * DD + e);
            a0 = fmaf(us[0][d], w, a0);
            a1 = fmaf(us[1][d], w, a1);
            a2 = fmaf(us[2][d], w, a2);
            a3 = fmaf(us[3][d], w, a3);
        }
        g_c[kq][(b0 + 0) * DD + e] = a0;
        g_c[kq][(b0 + 1) * DD + e] = a1;
        g_c[kq][(b0 + 2) * DD + e] = a2;
        g_c[kq][(b0 + 3) * DD + e] = a3;
    }
}

// ---------------- kernel 1: fused GEMM(mma.16816) + tanh + bias-dot ----------------
// grid = 1024: mtile(256) x ntile(4). CTA 512 thr: tile M=128 x N=256, K=1024.
// A: fp32 LDG (stage+2 into regs) -> cvt -> STS (stage+1).  B: cp.async fp16.
__global__ void __launch_bounds__(512, 1) main_kernel(const float* __restrict__ x,
                                                      const float* __restrict__ bias) {
    extern __shared__ char smem[];
    const uint32_t sb = smem_u32(smem);
    const int tid  = threadIdx.x;
    const int w    = tid >> 5, lane = tid & 31;
    const int wm   = w >> 2,  wn   = w & 3;
    const int nt    = blockIdx.x & 3;
    const int m0    = (blockIdx.x >> 2) * 128;
    const int b     = m0 >> 9;

    float* c_sm  = reinterpret_cast<float*>(smem + OFF_C);
    float* bi_sm = reinterpret_cast<float*>(smem + OFF_BI);
    if (tid < 256) {
        const int ce = nt * 256 + tid;
        c_sm[tid]  = g_c[0][b * DD + ce] + g_c[1][b * DD + ce]
                   + g_c[2][b * DD + ce] + g_c[3][b * DD + ce];
        bi_sm[tid] = bias[ce];
    }

    const float*  Ax = x + (size_t)(b * 513 + 1 + (m0 & 511)) * DD;   // 128 z-rows
    const __half* Bb = g_wzT + (size_t)nt * 256 * DD;

    // per-thread A geometry: 4 float4 per chunk (i = tid + j*512)
    const int aR0 = tid >> 4;            // + j*32, row in [0,128)
    const int aC4 = tid & 15;            // float4 col within 64-float chunk

    auto ldgA = [&](int kc, float4* apf) {
#pragma unroll
        for (int j = 0; j < 4; j++)
            apf[j] = __ldg(reinterpret_cast<const float4*>(Ax + (size_t)(aR0 + j * 32) * DD + kc * 64) + aC4);
    };
    auto stsA = [&](int s, const float4* apf) {
#pragma unroll
        for (int j = 0; j < 4; j++) {
            const int row = aR0 + j * 32;
            __half2 h0 = __floats2half2_rn(apf[j].x, apf[j].y);
            __half2 h1 = __floats2half2_rn(apf[j].z, apf[j].w);
            uint32_t u0 = *reinterpret_cast<const uint32_t*>(&h0);
            uint32_t u1 = *reinterpret_cast<const uint32_t*>(&h1);
            uint32_t dst = sb + OFF_SA + s * SA_ST + row * 128
                         + ((((aC4 >> 1) ^ (row & 7)) << 4) + ((aC4 & 1) << 3));
            asm volatile("st.shared.v2.b32 [%0], {%1, %2};" :: "r"(dst), "r"(u0), "r"(u1) : "memory");
        }
    };
    auto issueB = [&](int kc, int s) {
#pragma unroll
        for (int j = 0; j < 4; j++) {   // B: 256 rows x 8 segs = 2048 x 16B
            int i = tid + j * 512;
            int row = i >> 3, v = i & 7;
            uint32_t dst = sb + OFF_SB + s * SB_ST + row * 128 + ((v ^ (row & 7)) << 4);
            CP16(dst, Bb + (size_t)row * DD + kc * 64 + v * 8);
        }
        CP_COMMIT();
    };

    float acc[2][8][4];
#pragma unroll
    for (int mi = 0; mi < 2; mi++)
#pragma unroll
        for (int nj = 0; nj < 8; nj++)
#pragma unroll
            for (int r = 0; r < 4; r++) acc[mi][nj][r] = 0.0f;

    // per-lane ldmatrix geometry
    const int aRow  = wm * 32 + (lane & 15);            // + mi*16
    const int aBit  = lane >> 4;
    const int aSw   = aRow & 7;
    const int bRowL = (lane & 7) + ((lane >> 4) << 3);  // + wn*64 + g*16
    const int bBit  = (lane >> 3) & 1;

    // prologue
    float4 apf[4];
    ldgA(0, apf);
    stsA(0, apf);         // A0 -> stage 0 (visible after first barrier)
    ldgA(1, apf);         // A1 in regs
    issueB(0, 0);
    issueB(1, 1);

    for (int kc = 0; kc < 16; kc++) {
        if (kc == 15) { CP_WAIT(0); } else { CP_WAIT(1); }
        __syncthreads();
        if (kc < 15) stsA((kc + 1) % 3, apf);            // A(kc+1), regs loaded last iter
        if (kc < 14) { ldgA(kc + 2, apf); issueB(kc + 2, (kc + 2) % 3); }

        const int s = kc % 3;
        const uint32_t aBase = sb + OFF_SA + s * SA_ST + aRow * 128;
        const uint32_t bBase = sb + OFF_SB + s * SB_ST;
#pragma unroll
        for (int ks = 0; ks < 4; ks++) {
            uint32_t a[2][4];
#pragma unroll
            for (int mi = 0; mi < 2; mi++) {
                uint32_t addr = aBase + mi * (16 * 128) + ((((ks * 2) + aBit) ^ aSw) << 4);
                LDSM_X4(a[mi][0], a[mi][1], a[mi][2], a[mi][3], addr);
            }
#pragma unroll
            for (int g = 0; g < 4; g++) {
                const int nrow = wn * 64 + g * 16 + bRowL;
                uint32_t addr = bBase + nrow * 128 + ((((ks * 2) + bBit) ^ (nrow & 7)) << 4);
                uint32_t r0, r1, r2, r3;
                LDSM_X4(r0, r1, r2, r3, addr);
                MMA16816(acc[0][2 * g],     a[0], r0, r1);
                MMA16816(acc[1][2 * g],     a[1], r0, r1);
                MMA16816(acc[0][2 * g + 1], a[0], r2, r3);
                MMA16816(acc[1][2 * g + 1], a[1], r2, r3);
            }
        }
    }

    // ---- epilogue (registers): +c -> tanh -> *bias -> row partials ----
    const int colb = wn * 64 + 2 * (lane & 3);
    float p[4] = {0.f, 0.f, 0.f, 0.f};
#pragma unroll
    for (int mi = 0; mi < 2; mi++)
#pragma unroll
        for (int nj = 0; nj < 8; nj++) {
            const int c0 = colb + nj * 8;
            p[2 * mi + 0] = fmaf(fast_tanh(acc[mi][nj][0] + c_sm[c0]),     bi_sm[c0],     p[2 * mi + 0]);
            p[2 * mi + 0] = fmaf(fast_tanh(acc[mi][nj][1] + c_sm[c0 + 1]), bi_sm[c0 + 1], p[2 * mi + 0]);
            p[2 * mi + 1] = fmaf(fast_tanh(acc[mi][nj][2] + c_sm[c0]),     bi_sm[c0],     p[2 * mi + 1]);
            p[2 * mi + 1] = fmaf(fast_tanh(acc[mi][nj][3] + c_sm[c0 + 1]), bi_sm[c0 + 1], p[2 * mi + 1]);
        }
#pragma unroll
    for (int i = 0; i < 4; i++) {
        p[i] += __shfl_xor_sync(0xffffffffu, p[i], 1);
        p[i] += __shfl_xor_sync(0xffffffffu, p[i], 2);
    }
    float* qb = reinterpret_cast<float*>(smem + OFF_QB);
    if ((lane & 3) == 0) {
        const int r = wm * 32 + (lane >> 2);
        qb[wn * 128 + r +  0] = p[0];
        qb[wn * 128 + r +  8] = p[1];
        qb[wn * 128 + r + 16] = p[2];
        qb[wn * 128 + r + 24] = p[3];
    }
    __syncthreads();
    if (tid < 128) {
        float s = qb[tid] + qb[128 + tid] + qb[256 + tid] + qb[384 + tid];
        g_qp[(size_t)nt * MROWS + m0 + tid] = s;
    }
}

// ---------------- kernel 2: softmax over k=512 per batch ----------------
__global__ void __launch_bounds__(512) softmax_kernel(float* __restrict__ out) {
    __shared__ float sred[16];
    __shared__ float sbc;
    const int b = blockIdx.x, t = threadIdx.x;
    const int wid = t >> 5, lid = t & 31;
    const int idx = b * NKK + t;
    float v = g_qp[idx] + g_qp[MROWS + idx] + g_qp[2 * MROWS + idx] + g_qp[3 * MROWS + idx];

    float m = v;
#pragma unroll
    for (int o = 16; o; o >>= 1) m = fmaxf(m, __shfl_xor_sync(0xffffffffu, m, o));
    if (lid == 0) sred[wid] = m;
    __syncthreads();
    if (wid == 0) {
        float mm = (lid < 16) ? sred[lid] : -1e30f;
#pragma unroll
        for (int o = 16; o; o >>= 1) mm = fmaxf(mm, __shfl_xor_sync(0xffffffffu, mm, o));
        if (lid == 0) sbc = mm;
    }
    __syncthreads();
    const float M = sbc;
    float e;
    asm("ex2.approx.f32 %0, %1;" : "=f"(e) : "f"((v - M) * 1.4426950408889634f));
    float s = e;
#pragma unroll
    for (int o = 16; o; o >>= 1) s += __shfl_xor_sync(0xffffffffu, s, o);
    __syncthreads();
    if (lid == 0) sred[wid] = s;
    __syncthreads();
    if (wid == 0) {
        float ss = (lid < 16) ? sred[lid] : 0.f;
#pragma unroll
        for (int o = 16; o; o >>= 1) ss += __shfl_xor_sync(0xffffffffu, ss, o);
        if (lid == 0) sbc = ss;
    }
    __syncthreads();
    out[idx] = e / sbc;
}

// ---------------- launch ----------------
extern "C" void kernel_launch(void* const* d_in, const int* in_sizes, int n_in,
                              void* d_out, int out_size) {
    const float* x    = (const float*)d_in[0];
    const float* W    = (const float*)d_in[1];
    const float* bias = (const float*)d_in[2];
    float* out = (float*)d_out;

    cudaFuncSetAttribute(main_kernel, cudaFuncAttributeMaxDynamicSharedMemorySize, SMEM_MAIN);

    prep_kernel<<<1280, 256>>>(x, W);
    main_kernel<<<1024, 512, SMEM_MAIN>>>(x, bias);
    softmax_kernel<<<64, 512>>>(out);
}

// round 6
// speedup vs baseline: 1.8140x; 1.1602x over previous
#include <cuda_runtime.h>
#include <cuda_fp16.h>
#include <cstdint>

#define DD  1024
#define NB  64
#define NKK 512
#define MROWS (NB * NKK)          // 32768 flattened z-rows

// ---------------- device scratch (no allocs allowed) ----------------
__device__ __half g_wzT[DD * DD];            // w_z transposed fp16: [e][d]
__device__ float  g_c[16][NB * DD];          // split-K partials of c[b,e]
__device__ float  g_qp[4 * MROWS];           // partial q per n-tile

// ---------------- helpers ----------------
static __device__ __forceinline__ uint32_t smem_u32(const void* p) {
    uint32_t a;
    asm("{ .reg .u64 t; cvta.to.shared.u64 t, %1; cvt.u32.u64 %0, t; }" : "=r"(a) : "l"(p));
    return a;
}
#define CP16(dst, src) \
    asm volatile("cp.async.cg.shared.global [%0], [%1], 16;" :: "r"(dst), "l"(src))
#define CP_COMMIT() asm volatile("cp.async.commit_group;" ::: "memory")
#define CP_WAIT(n)  asm volatile("cp.async.wait_group %0;" :: "n"(n) : "memory")

#define LDSM_X4(r0, r1, r2, r3, addr) \
    asm volatile("ldmatrix.sync.aligned.m8n8.x4.shared.b16 {%0,%1,%2,%3}, [%4];" \
        : "=r"(r0), "=r"(r1), "=r"(r2), "=r"(r3) : "r"(addr))

#define MMA16816(d, a, b0, b1) \
    asm volatile("mma.sync.aligned.m16n8k16.row.col.f32.f16.f16.f32 " \
        "{%0,%1,%2,%3}, {%4,%5,%6,%7}, {%8,%9}, {%0,%1,%2,%3};" \
        : "+f"((d)[0]), "+f"((d)[1]), "+f"((d)[2]), "+f"((d)[3]) \
        : "r"((a)[0]), "r"((a)[1]), "r"((a)[2]), "r"((a)[3]), "r"(b0), "r"(b1))

// exact identity tanh(x) = 1 - 2/(e^{2x}+1), via ex2.approx + rcp.approx (~1e-6)
static __device__ __forceinline__ float fast_tanh(float x) {
    float e;
    asm("ex2.approx.f32 %0, %1;" : "=f"(e) : "f"(x * 2.885390081777927f)); // 2*log2(e)
    float r;
    asm("rcp.approx.f32 %0, %1;" : "=f"(r) : "f"(e + 1.0f));
    return fmaf(-2.0f, r, 1.0f);
}

// ---------------- SMEM layout of the main kernel (XOR-swizzled 128B rows) --------
static constexpr int SA_ST   = 128 * 128;              // 16 KB per stage (fp16)
static constexpr int SB_ST   = 256 * 128;              // 32 KB per stage
static constexpr int OFF_SA  = 0;
static constexpr int OFF_SB  = 3 * SA_ST;              // 49152
static constexpr int OFF_C   = OFF_SB + 3 * SB_ST;     // 147456
static constexpr int OFF_BI  = OFF_C + 1024;
static constexpr int OFF_QB  = OFF_BI + 1024;
static constexpr int SMEM_MAIN = OFF_QB + 2048;        // 151552

// ---------------- prep kernel: w_z transpose->fp16 | split-K cvec ----------------
// blocks [0,1024): transpose ; [1024,2048): cvec partials (d-split by 16)
__global__ void __launch_bounds__(256) prep_kernel(const float* __restrict__ x,
                                                   const float* __restrict__ W) {
    __shared__ float psm[33 * 32];     // union: 32x33 f32 tile | 4 x 64 u-slice
    const int bid = blockIdx.x, t = threadIdx.x;

    if (bid < 1024) {                 // ---- transpose w_z -> g_wzT fp16 ----
        float (*tile)[33] = reinterpret_cast<float (*)[33]>(psm);
        const int d0 = (bid & 31) * 32, e0 = (bid >> 5) * 32;
        const int tx = t & 31, ty = t >> 5;          // (32, 8)
#pragma unroll
        for (int i = 0; i < 32; i += 8)
            tile[ty + i][tx] = W[(size_t)(d0 + ty + i) * DD + e0 + tx];
        __syncthreads();
#pragma unroll
        for (int i = 0; i < 32; i += 8)
            g_wzT[(size_t)(e0 + ty + i) * DD + d0 + tx] = __float2half(tile[tx][ty + i]);
    } else {                          // ---- cvec partial: sum over 64 d's ----
        const int idx = bid - 1024;                  // 1024 blocks
        const int e  = (idx & 3) * 256 + t;          // e-chunk
        const int b0 = ((idx >> 2) & 15) * 4;        // 4 batches
        const int kq = idx >> 6;                     // d-sixteenth (64 d's)
        float (*us)[64] = reinterpret_cast<float (*)[64]>(psm);
        if (t < 256) {
            int j = t >> 6, d = t & 63;
            us[j][d] = x[(size_t)(b0 + j) * 513 * DD + kq * 64 + d];
        }
        __syncthreads();
        const float* wu = W + (size_t)DD * DD + (size_t)kq * 64 * DD;
        float a0 = 0, a1 = 0, a2 = 0, a3 = 0;
#pragma unroll 8
        for (int d = 0; d < 64; d++) {
            float w = __ldg(wu + (size_t)d * DD + e);
            a0 = fmaf(us[0][d], w, a0);
            a1 = fmaf(us[1][d], w, a1);
            a2 = fmaf(us[2][d], w, a2);
            a3 = fmaf(us[3][d], w, a3);
        }
        g_c[kq][(b0 + 0) * DD + e] = a0;
        g_c[kq][(b0 + 1) * DD + e] = a1;
        g_c[kq][(b0 + 2) * DD + e] = a2;
        g_c[kq][(b0 + 3) * DD + e] = a3;
    }
}

// ---------------- kernel 1: fused GEMM(mma.16816) + tanh + bias-dot ----------------
// grid = 1024: mtile(256) x ntile(4). CTA 512 thr: tile M=128 x N=256, K=1024.
// A: fp32 LDG (stage+2 into regs) -> cvt -> STS (stage+1).  B: cp.async fp16.
__global__ void __launch_bounds__(512, 1) main_kernel(const float* __restrict__ x,
                                                      const float* __restrict__ bias) {
    extern __shared__ char smem[];
    const uint32_t sb = smem_u32(smem);
    const int tid  = threadIdx.x;
    const int w    = tid >> 5, lane = tid & 31;
    const int wm   = w >> 2,  wn   = w & 3;
    const int nt    = blockIdx.x & 3;
    const int m0    = (blockIdx.x >> 2) * 128;
    const int b     = m0 >> 9;

    float* c_sm  = reinterpret_cast<float*>(smem + OFF_C);
    float* bi_sm = reinterpret_cast<float*>(smem + OFF_BI);
    if (tid < 256) {
        const int off = b * DD + nt * 256 + tid;
        float s0 = 0.f, s1 = 0.f, s2 = 0.f, s3 = 0.f;
#pragma unroll
        for (int i = 0; i < 4; i++) {
            s0 += g_c[4 * i + 0][off];
            s1 += g_c[4 * i + 1][off];
            s2 += g_c[4 * i + 2][off];
            s3 += g_c[4 * i + 3][off];
        }
        c_sm[tid]  = (s0 + s1) + (s2 + s3);
        bi_sm[tid] = bias[nt * 256 + tid];
    }

    const float*  Ax = x + (size_t)(b * 513 + 1 + (m0 & 511)) * DD;   // 128 z-rows
    const __half* Bb = g_wzT + (size_t)nt * 256 * DD;

    // per-thread A geometry: 4 float4 per chunk (i = tid + j*512)
    const int aR0 = tid >> 4;            // + j*32, row in [0,128)
    const int aC4 = tid & 15;            // float4 col within 64-float chunk

    auto ldgA = [&](int kc, float4* apf) {
#pragma unroll
        for (int j = 0; j < 4; j++)
            apf[j] = __ldg(reinterpret_cast<const float4*>(Ax + (size_t)(aR0 + j * 32) * DD + kc * 64) + aC4);
    };
    auto stsA = [&](int s, const float4* apf) {
#pragma unroll
        for (int j = 0; j < 4; j++) {
            const int row = aR0 + j * 32;
            __half2 h0 = __floats2half2_rn(apf[j].x, apf[j].y);
            __half2 h1 = __floats2half2_rn(apf[j].z, apf[j].w);
            uint32_t u0 = *reinterpret_cast<const uint32_t*>(&h0);
            uint32_t u1 = *reinterpret_cast<const uint32_t*>(&h1);
            uint32_t dst = sb + OFF_SA + s * SA_ST + row * 128
                         + ((((aC4 >> 1) ^ (row & 7)) << 4) + ((aC4 & 1) << 3));
            asm volatile("st.shared.v2.b32 [%0], {%1, %2};" :: "r"(dst), "r"(u0), "r"(u1) : "memory");
        }
    };
    auto issueB = [&](int kc, int s) {
#pragma unroll
        for (int j = 0; j < 4; j++) {   // B: 256 rows x 8 segs = 2048 x 16B
            int i = tid + j * 512;
            int row = i >> 3, v = i & 7;
            uint32_t dst = sb + OFF_SB + s * SB_ST + row * 128 + ((v ^ (row & 7)) << 4);
            CP16(dst, Bb + (size_t)row * DD + kc * 64 + v * 8);
        }
        CP_COMMIT();
    };

    float acc[2][8][4];
#pragma unroll
    for (int mi = 0; mi < 2; mi++)
#pragma unroll
        for (int nj = 0; nj < 8; nj++)
#pragma unroll
            for (int r = 0; r < 4; r++) acc[mi][nj][r] = 0.0f;

    // per-lane ldmatrix geometry
    const int aRow  = wm * 32 + (lane & 15);            // + mi*16
    const int aBit  = lane >> 4;
    const int aSw   = aRow & 7;
    const int bRowL = (lane & 7) + ((lane >> 4) << 3);  // + wn*64 + g*16
    const int bBit  = (lane >> 3) & 1;

    // prologue
    float4 apf[4];
    ldgA(0, apf);
    stsA(0, apf);         // A0 -> stage 0 (visible after first barrier)
    ldgA(1, apf);         // A1 in regs
    issueB(0, 0);
    issueB(1, 1);

    for (int kc = 0; kc < 16; kc++) {
        // STS A(kc+1) BEFORE the barrier: writes stage (kc+1)%3, which no warp
        // (even one lagging in iteration kc-1) can be reading; overlaps barrier drain.
        if (kc < 15) stsA((kc + 1) % 3, apf);
        if (kc == 15) { CP_WAIT(0); } else { CP_WAIT(1); }
        __syncthreads();
        if (kc < 14) { ldgA(kc + 2, apf); issueB(kc + 2, (kc + 2) % 3); }

        const int s = kc % 3;
        const uint32_t aBase = sb + OFF_SA + s * SA_ST + aRow * 128;
        const uint32_t bBase = sb + OFF_SB + s * SB_ST;
#pragma unroll
        for (int ks = 0; ks < 4; ks++) {
            uint32_t a[2][4];
#pragma unroll
            for (int mi = 0; mi < 2; mi++) {
                uint32_t addr = aBase + mi * (16 * 128) + ((((ks * 2) + aBit) ^ aSw) << 4);
                LDSM_X4(a[mi][0], a[mi][1], a[mi][2], a[mi][3], addr);
            }
#pragma unroll
            for (int g = 0; g < 4; g++) {
                const int nrow = wn * 64 + g * 16 + bRowL;
                uint32_t addr = bBase + nrow * 128 + ((((ks * 2) + bBit) ^ (nrow & 7)) << 4);
                uint32_t r0, r1, r2, r3;
                LDSM_X4(r0, r1, r2, r3, addr);
                MMA16816(acc[0][2 * g],     a[0], r0, r1);
                MMA16816(acc[1][2 * g],     a[1], r0, r1);
                MMA16816(acc[0][2 * g + 1], a[0], r2, r3);
                MMA16816(acc[1][2 * g + 1], a[1], r2, r3);
            }
        }
    }

    // ---- epilogue (registers): +c -> tanh -> *bias -> row partials ----
    const int colb = wn * 64 + 2 * (lane & 3);
    float p[4] = {0.f, 0.f, 0.f, 0.f};
#pragma unroll
    for (int mi = 0; mi < 2; mi++)
#pragma unroll
        for (int nj = 0; nj < 8; nj++) {
            const int c0 = colb + nj * 8;
            p[2 * mi + 0] = fmaf(fast_tanh(acc[mi][nj][0] + c_sm[c0]),     bi_sm[c0],     p[2 * mi + 0]);
            p[2 * mi + 0] = fmaf(fast_tanh(acc[mi][nj][1] + c_sm[c0 + 1]), bi_sm[c0 + 1], p[2 * mi + 0]);
            p[2 * mi + 1] = fmaf(fast_tanh(acc[mi][nj][2] + c_sm[c0]),     bi_sm[c0],     p[2 * mi + 1]);
            p[2 * mi + 1] = fmaf(fast_tanh(acc[mi][nj][3] + c_sm[c0 + 1]), bi_sm[c0 + 1], p[2 * mi + 1]);
        }
#pragma unroll
    for (int i = 0; i < 4; i++) {
        p[i] += __shfl_xor_sync(0xffffffffu, p[i], 1);
        p[i] += __shfl_xor_sync(0xffffffffu, p[i], 2);
    }
    float* qb = reinterpret_cast<float*>(smem + OFF_QB);
    if ((lane & 3) == 0) {
        const int r = wm * 32 + (lane >> 2);
        qb[wn * 128 + r +  0] = p[0];
        qb[wn * 128 + r +  8] = p[1];
        qb[wn * 128 + r + 16] = p[2];
        qb[wn * 128 + r + 24] = p[3];
    }
    __syncthreads();
    if (tid < 128) {
        float s = qb[tid] + qb[128 + tid] + qb[256 + tid] + qb[384 + tid];
        g_qp[(size_t)nt * MROWS + m0 + tid] = s;
    }
}

// ---------------- kernel 2: softmax over k=512 per batch ----------------
__global__ void __launch_bounds__(512) softmax_kernel(float* __restrict__ out) {
    __shared__ float sred[16];
    __shared__ float sbc;
    const int b = blockIdx.x, t = threadIdx.x;
    const int wid = t >> 5, lid = t & 31;
    const int idx = b * NKK + t;
    float v = g_qp[idx] + g_qp[MROWS + idx] + g_qp[2 * MROWS + idx] + g_qp[3 * MROWS + idx];

    float m = v;
#pragma unroll
    for (int o = 16; o; o >>= 1) m = fmaxf(m, __shfl_xor_sync(0xffffffffu, m, o));
    if (lid == 0) sred[wid] = m;
    __syncthreads();
    if (wid == 0) {
        float mm = (lid < 16) ? sred[lid] : -1e30f;
#pragma unroll
        for (int o = 16; o; o >>= 1) mm = fmaxf(mm, __shfl_xor_sync(0xffffffffu, mm, o));
        if (lid == 0) sbc = mm;
    }
    __syncthreads();
    const float M = sbc;
    float e;
    asm("ex2.approx.f32 %0, %1;" : "=f"(e) : "f"((v - M) * 1.4426950408889634f));
    float s = e;
#pragma unroll
    for (int o = 16; o; o >>= 1) s += __shfl_xor_sync(0xffffffffu, s, o);
    __syncthreads();
    if (lid == 0) sred[wid] = s;
    __syncthreads();
    if (wid == 0) {
        float ss = (lid < 16) ? sred[lid] : 0.f;
#pragma unroll
        for (int o = 16; o; o >>= 1) ss += __shfl_xor_sync(0xffffffffu, ss, o);
        if (lid == 0) sbc = ss;
    }
    __syncthreads();
    out[idx] = e / sbc;
}

// ---------------- launch ----------------
extern "C" void kernel_launch(void* const* d_in, const int* in_sizes, int n_in,
                              void* d_out, int out_size) {
    const float* x    = (const float*)d_in[0];
    const float* W    = (const float*)d_in[1];
    const float* bias = (const float*)d_in[2];
    float* out = (float*)d_out;

    cudaFuncSetAttribute(main_kernel, cudaFuncAttributeMaxDynamicSharedMemorySize, SMEM_MAIN);

    prep_kernel<<<2048, 256>>>(x, W);
    main_kernel<<<1024, 512, SMEM_MAIN>>>(x, bias);
    softmax_kernel<<<64, 512>>>(out);
}

// round 7
// speedup vs baseline: 1.8690x; 1.0303x over previous
#include <cuda_runtime.h>
#include <cuda_fp16.h>
#include <cstdint>

#define DD  1024
#define NB  64
#define NKK 512
#define MROWS (NB * NKK)          // 32768 flattened z-rows

// ---------------- device scratch (no allocs allowed) ----------------
__device__ __half g_wzT[DD * DD];            // w_z transposed fp16: [e][d]
__device__ float  g_c[16][NB * DD];          // split-K partials of c[b,e]
__device__ float  g_qp[4 * MROWS];           // partial q per n-tile

// ---------------- helpers ----------------
static __device__ __forceinline__ uint32_t smem_u32(const void* p) {
    uint32_t a;
    asm("{ .reg .u64 t; cvta.to.shared.u64 t, %1; cvt.u32.u64 %0, t; }" : "=r"(a) : "l"(p));
    return a;
}
#define CP16(dst, src) \
    asm volatile("cp.async.cg.shared.global [%0], [%1], 16;" :: "r"(dst), "l"(src))
#define CP_COMMIT() asm volatile("cp.async.commit_group;" ::: "memory")
#define CP_WAIT(n)  asm volatile("cp.async.wait_group %0;" :: "n"(n) : "memory")

#define LDSM_X4(r0, r1, r2, r3, addr) \
    asm volatile("ldmatrix.sync.aligned.m8n8.x4.shared.b16 {%0,%1,%2,%3}, [%4];" \
        : "=r"(r0), "=r"(r1), "=r"(r2), "=r"(r3) : "r"(addr))

#define MMA16816(d, a, b0, b1) \
    asm volatile("mma.sync.aligned.m16n8k16.row.col.f32.f16.f16.f32 " \
        "{%0,%1,%2,%3}, {%4,%5,%6,%7}, {%8,%9}, {%0,%1,%2,%3};" \
        : "+f"((d)[0]), "+f"((d)[1]), "+f"((d)[2]), "+f"((d)[3]) \
        : "r"((a)[0]), "r"((a)[1]), "r"((a)[2]), "r"((a)[3]), "r"(b0), "r"(b1))

// exact identity tanh(x) = 1 - 2/(e^{2x}+1), via ex2.approx + rcp.approx (~1e-6)
static __device__ __forceinline__ float fast_tanh(float x) {
    float e;
    asm("ex2.approx.f32 %0, %1;" : "=f"(e) : "f"(x * 2.885390081777927f)); // 2*log2(e)
    float r;
    asm("rcp.approx.f32 %0, %1;" : "=f"(r) : "f"(e + 1.0f));
    return fmaf(-2.0f, r, 1.0f);
}

// ---------------- SMEM layout of the main kernel (XOR-swizzled 128B rows) --------
static constexpr int SA_ST   = 128 * 128;              // 16 KB per stage (fp16)
static constexpr int SB_ST   = 256 * 128;              // 32 KB per stage
static constexpr int OFF_SA  = 0;
static constexpr int OFF_SB  = 3 * SA_ST;              // 49152
static constexpr int OFF_C   = OFF_SB + 3 * SB_ST;     // 147456
static constexpr int OFF_BI  = OFF_C + 1024;
static constexpr int OFF_QB  = OFF_BI + 1024;
static constexpr int SMEM_MAIN = OFF_QB + 2048;        // 151552

// ---------------- prep kernel: w_z transpose->fp16 | split-K cvec ----------------
// blocks [0,1024): transpose ; [1024,2048): cvec partials (d-split by 16)
__global__ void __launch_bounds__(256) prep_kernel(const float* __restrict__ x,
                                                   const float* __restrict__ W) {
    __shared__ float psm[33 * 32];     // union: 32x33 f32 tile | 4 x 64 u-slice
    const int bid = blockIdx.x, t = threadIdx.x;

    if (bid < 1024) {                 // ---- transpose w_z -> g_wzT fp16 ----
        float (*tile)[33] = reinterpret_cast<float (*)[33]>(psm);
        const int d0 = (bid & 31) * 32, e0 = (bid >> 5) * 32;
        const int tx = t & 31, ty = t >> 5;          // (32, 8)
#pragma unroll
        for (int i = 0; i < 32; i += 8)
            tile[ty + i][tx] = W[(size_t)(d0 + ty + i) * DD + e0 + tx];
        __syncthreads();
#pragma unroll
        for (int i = 0; i < 32; i += 8)
            g_wzT[(size_t)(e0 + ty + i) * DD + d0 + tx] = __float2half(tile[tx][ty + i]);
    } else {                          // ---- cvec partial: sum over 64 d's ----
        const int idx = bid - 1024;                  // 1024 blocks
        const int e  = (idx & 3) * 256 + t;          // e-chunk
        const int b0 = ((idx >> 2) & 15) * 4;        // 4 batches
        const int kq = idx >> 6;                     // d-sixteenth (64 d's)
        float (*us)[64] = reinterpret_cast<float (*)[64]>(psm);
        if (t < 256) {
            int j = t >> 6, d = t & 63;
            us[j][d] = x[(size_t)(b0 + j) * 513 * DD + kq * 64 + d];
        }
        __syncthreads();
        const float* wu = W + (size_t)DD * DD + (size_t)kq * 64 * DD;
        float a0 = 0, a1 = 0, a2 = 0, a3 = 0;
#pragma unroll 8
        for (int d = 0; d < 64; d++) {
            float w = __ldg(wu + (size_t)d * DD + e);
            a0 = fmaf(us[0][d], w, a0);
            a1 = fmaf(us[1][d], w, a1);
            a2 = fmaf(us[2][d], w, a2);
            a3 = fmaf(us[3][d], w, a3);
        }
        g_c[kq][(b0 + 0) * DD + e] = a0;
        g_c[kq][(b0 + 1) * DD + e] = a1;
        g_c[kq][(b0 + 2) * DD + e] = a2;
        g_c[kq][(b0 + 3) * DD + e] = a3;
    }
}

// ---------------- kernel 1: fused GEMM(mma.16816) + tanh + bias-dot ----------------
// grid = 1024: mtile(256) x ntile(4). CTA 512 thr: tile M=128 x N=256, K=1024.
// A: fp32 LDG (stage+2 into regs) -> cvt -> STS (stage+1).  B: cp.async fp16.
// Inner loop: fragment double-buffer; LDSM prefetched one group ahead of its MMAs.
__global__ void __launch_bounds__(512, 1) main_kernel(const float* __restrict__ x,
                                                      const float* __restrict__ bias) {
    extern __shared__ char smem[];
    const uint32_t sb = smem_u32(smem);
    const int tid  = threadIdx.x;
    const int w    = tid >> 5, lane = tid & 31;
    const int wm   = w >> 2,  wn   = w & 3;
    const int nt    = blockIdx.x & 3;
    const int m0    = (blockIdx.x >> 2) * 128;
    const int b     = m0 >> 9;

    float* c_sm  = reinterpret_cast<float*>(smem + OFF_C);
    float* bi_sm = reinterpret_cast<float*>(smem + OFF_BI);
    if (tid < 256) {
        const int off = b * DD + nt * 256 + tid;
        float s0 = 0.f, s1 = 0.f, s2 = 0.f, s3 = 0.f;
#pragma unroll
        for (int i = 0; i < 4; i++) {
            s0 += g_c[4 * i + 0][off];
            s1 += g_c[4 * i + 1][off];
            s2 += g_c[4 * i + 2][off];
            s3 += g_c[4 * i + 3][off];
        }
        c_sm[tid]  = (s0 + s1) + (s2 + s3);
        bi_sm[tid] = bias[nt * 256 + tid];
    }

    const float*  Ax = x + (size_t)(b * 513 + 1 + (m0 & 511)) * DD;   // 128 z-rows
    const __half* Bb = g_wzT + (size_t)nt * 256 * DD;

    // per-thread A geometry: 4 float4 per chunk (i = tid + j*512)
    const int aR0 = tid >> 4;            // + j*32, row in [0,128)
    const int aC4 = tid & 15;            // float4 col within 64-float chunk

    auto ldgA = [&](int kc, float4* apf) {
#pragma unroll
        for (int j = 0; j < 4; j++)
            apf[j] = __ldg(reinterpret_cast<const float4*>(Ax + (size_t)(aR0 + j * 32) * DD + kc * 64) + aC4);
    };
    auto stsA = [&](int s, const float4* apf) {
#pragma unroll
        for (int j = 0; j < 4; j++) {
            const int row = aR0 + j * 32;
            __half2 h0 = __floats2half2_rn(apf[j].x, apf[j].y);
            __half2 h1 = __floats2half2_rn(apf[j].z, apf[j].w);
            uint32_t u0 = *reinterpret_cast<const uint32_t*>(&h0);
            uint32_t u1 = *reinterpret_cast<const uint32_t*>(&h1);
            uint32_t dst = sb + OFF_SA + s * SA_ST + row * 128
                         + ((((aC4 >> 1) ^ (row & 7)) << 4) + ((aC4 & 1) << 3));
            asm volatile("st.shared.v2.b32 [%0], {%1, %2};" :: "r"(dst), "r"(u0), "r"(u1) : "memory");
        }
    };
    auto issueB = [&](int kc, int s) {
#pragma unroll
        for (int j = 0; j < 4; j++) {   // B: 256 rows x 8 segs = 2048 x 16B
            int i = tid + j * 512;
            int row = i >> 3, v = i & 7;
            uint32_t dst = sb + OFF_SB + s * SB_ST + row * 128 + ((v ^ (row & 7)) << 4);
            CP16(dst, Bb + (size_t)row * DD + kc * 64 + v * 8);
        }
        CP_COMMIT();
    };

    float acc[2][8][4];
#pragma unroll
    for (int mi = 0; mi < 2; mi++)
#pragma unroll
        for (int nj = 0; nj < 8; nj++)
#pragma unroll
            for (int r = 0; r < 4; r++) acc[mi][nj][r] = 0.0f;

    // per-lane ldmatrix geometry
    const int aRow  = wm * 32 + (lane & 15);            // + mi*16
    const int aBit  = lane >> 4;
    const int aSw   = aRow & 7;
    const int bRowL = (lane & 7) + ((lane >> 4) << 3);  // + wn*64 + g*16
    const int bBit  = (lane >> 3) & 1;

    // prologue
    float4 apf[4];
    ldgA(0, apf);
    stsA(0, apf);         // A0 -> stage 0 (visible after first barrier)
    ldgA(1, apf);         // A1 in regs
    issueB(0, 0);
    issueB(1, 1);

    for (int kc = 0; kc < 16; kc++) {
        // STS A(kc+1) BEFORE the barrier: stage (kc+1)%3 is untouched by any
        // warp still in iteration kc-1 (it reads (kc-1)%3); overlaps barrier drain.
        if (kc < 15) stsA((kc + 1) % 3, apf);
        if (kc == 15) { CP_WAIT(0); } else { CP_WAIT(1); }
        __syncthreads();
        if (kc < 14) { ldgA(kc + 2, apf); issueB(kc + 2, (kc + 2) % 3); }

        const int s = kc % 3;
        const uint32_t aBase = sb + OFF_SA + s * SA_ST + aRow * 128;
        const uint32_t bBase = sb + OFF_SB + s * SB_ST;

        uint32_t afr[2][2][4];   // [buf][mi][reg]
        uint32_t bfr[2][4];      // [buf][reg]

        // chunk-head preload: A(ks=0) + B(ks=0, g=0)
#pragma unroll
        for (int mi = 0; mi < 2; mi++) {
            uint32_t addr = aBase + mi * (16 * 128) + ((aBit ^ aSw) << 4);
            LDSM_X4(afr[0][mi][0], afr[0][mi][1], afr[0][mi][2], afr[0][mi][3], addr);
        }
        {
            const int nrow = wn * 64 + bRowL;
            uint32_t addr = bBase + nrow * 128 + ((bBit ^ (nrow & 7)) << 4);
            LDSM_X4(bfr[0][0], bfr[0][1], bfr[0][2], bfr[0][3], addr);
        }

#pragma unroll
        for (int it = 0; it < 16; it++) {
            const int ks = it >> 2, g = it & 3;
            const int ab = ks & 1, bb2 = it & 1;
            // prefetch next fragments BEFORE this group's MMAs
            if (it < 15) {
                const int nit = it + 1, nks = nit >> 2, ng = nit & 3;
                const int nrow = wn * 64 + ng * 16 + bRowL;
                uint32_t baddr = bBase + nrow * 128 + ((((nks * 2) + bBit) ^ (nrow & 7)) << 4);
                LDSM_X4(bfr[bb2 ^ 1][0], bfr[bb2 ^ 1][1], bfr[bb2 ^ 1][2], bfr[bb2 ^ 1][3], baddr);
                if (ng == 0) {
#pragma unroll
                    for (int mi = 0; mi < 2; mi++) {
                        uint32_t aaddr = aBase + mi * (16 * 128) + ((((nks * 2) + aBit) ^ aSw) << 4);
                        LDSM_X4(afr[ab ^ 1][mi][0], afr[ab ^ 1][mi][1],
                                afr[ab ^ 1][mi][2], afr[ab ^ 1][mi][3], aaddr);
                    }
                }
            }
            MMA16816(acc[0][2 * g],     afr[ab][0], bfr[bb2][0], bfr[bb2][1]);
            MMA16816(acc[1][2 * g],     afr[ab][1], bfr[bb2][0], bfr[bb2][1]);
            MMA16816(acc[0][2 * g + 1], afr[ab][0], bfr[bb2][2], bfr[bb2][3]);
            MMA16816(acc[1][2 * g + 1], afr[ab][1], bfr[bb2][2], bfr[bb2][3]);
        }
    }

    // ---- epilogue (registers): +c -> tanh -> *bias -> row partials ----
    const int colb = wn * 64 + 2 * (lane & 3);
    float p[4] = {0.f, 0.f, 0.f, 0.f};
#pragma unroll
    for (int mi = 0; mi < 2; mi++)
#pragma unroll
        for (int nj = 0; nj < 8; nj++) {
            const int c0 = colb + nj * 8;
            p[2 * mi + 0] = fmaf(fast_tanh(acc[mi][nj][0] + c_sm[c0]),     bi_sm[c0],     p[2 * mi + 0]);
            p[2 * mi + 0] = fmaf(fast_tanh(acc[mi][nj][1] + c_sm[c0 + 1]), bi_sm[c0 + 1], p[2 * mi + 0]);
            p[2 * mi + 1] = fmaf(fast_tanh(acc[mi][nj][2] + c_sm[c0]),     bi_sm[c0],     p[2 * mi + 1]);
            p[2 * mi + 1] = fmaf(fast_tanh(acc[mi][nj][3] + c_sm[c0 + 1]), bi_sm[c0 + 1], p[2 * mi + 1]);
        }
#pragma unroll
    for (int i = 0; i < 4; i++) {
        p[i] += __shfl_xor_sync(0xffffffffu, p[i], 1);
        p[i] += __shfl_xor_sync(0xffffffffu, p[i], 2);
    }
    float* qb = reinterpret_cast<float*>(smem + OFF_QB);
    if ((lane & 3) == 0) {
        const int r = wm * 32 + (lane >> 2);
        qb[wn * 128 + r +  0] = p[0];
        qb[wn * 128 + r +  8] = p[1];
        qb[wn * 128 + r + 16] = p[2];
        qb[wn * 128 + r + 24] = p[3];
    }
    __syncthreads();
    if (tid < 128) {
        float s = qb[tid] + qb[128 + tid] + qb[256 + tid] + qb[384 + tid];
        g_qp[(size_t)nt * MROWS + m0 + tid] = s;
    }
}

// ---------------- kernel 2: softmax over k=512 per batch ----------------
__global__ void __launch_bounds__(512) softmax_kernel(float* __restrict__ out) {
    __shared__ float sred[16];
    __shared__ float sbc;
    const int b = blockIdx.x, t = threadIdx.x;
    const int wid = t >> 5, lid = t & 31;
    const int idx = b * NKK + t;
    float v = g_qp[idx] + g_qp[MROWS + idx] + g_qp[2 * MROWS + idx] + g_qp[3 * MROWS + idx];

    float m = v;
#pragma unroll
    for (int o = 16; o; o >>= 1) m = fmaxf(m, __shfl_xor_sync(0xffffffffu, m, o));
    if (lid == 0) sred[wid] = m;
    __syncthreads();
    if (wid == 0) {
        float mm = (lid < 16) ? sred[lid] : -1e30f;
#pragma unroll
        for (int o = 16; o; o >>= 1) mm = fmaxf(mm, __shfl_xor_sync(0xffffffffu, mm, o));
        if (lid == 0) sbc = mm;
    }
    __syncthreads();
    const float M = sbc;
    float e;
    asm("ex2.approx.f32 %0, %1;" : "=f"(e) : "f"((v - M) * 1.4426950408889634f));
    float s = e;
#pragma unroll
    for (int o = 16; o; o >>= 1) s += __shfl_xor_sync(0xffffffffu, s, o);
    __syncthreads();
    if (lid == 0) sred[wid] = s;
    __syncthreads();
    if (wid == 0) {
        float ss = (lid < 16) ? sred[lid] : 0.f;
#pragma unroll
        for (int o = 16; o; o >>= 1) ss += __shfl_xor_sync(0xffffffffu, ss, o);
        if (lid == 0) sbc = ss;
    }
    __syncthreads();
    out[idx] = e / sbc;
}

// ---------------- launch ----------------
extern "C" void kernel_launch(void* const* d_in, const int* in_sizes, int n_in,
                              void* d_out, int out_size) {
    const float* x    = (const float*)d_in[0];
    const float* W    = (const float*)d_in[1];
    const float* bias = (const float*)d_in[2];
    float* out = (float*)d_out;

    cudaFuncSetAttribute(main_kernel, cudaFuncAttributeMaxDynamicSharedMemorySize, SMEM_MAIN);

    prep_kernel<<<2048, 256>>>(x, W);
    main_kernel<<<1024, 512, SMEM_MAIN>>>(x, bias);
    softmax_kernel<<<64, 512>>>(out);
}